// round 16
// baseline (speedup 1.0000x reference)
#include <cuda_runtime.h>
#include <cuda_fp16.h>
#include <cstdint>
#include <math.h>

// ----------------------------------------------------------------------------
// Problem constants
// ----------------------------------------------------------------------------
#define S_LEN   2048
#define DMODEL  2048
#define HQ      32
#define HKV     8
#define HD      64
#define KV_DIM  (HKV*HD)   // 512
#define QKV_N   (DMODEL + 2 * KV_DIM)   // 3072

// ----------------------------------------------------------------------------
// Scratch (static __device__ arrays: allocation-free)
// ----------------------------------------------------------------------------
__device__ __half g_h[S_LEN * DMODEL];            // rmsnorm out fp16
__device__ __half g_wqkvt[QKV_N * DMODEL];        // [wq^T; wk^T; wv^T] fp16 [N,K]
__device__ __half g_wot[DMODEL * DMODEL];
__device__ __half g_pqkv[S_LEN * QKV_N];          // fused projection out (fp16)
__device__ __half g_q[S_LEN * DMODEL];            // roped+scaled q
__device__ __half g_k[S_LEN * KV_DIM];            // roped k
__device__ __half g_o[S_LEN * DMODEL];            // attn out

// ----------------------------------------------------------------------------
// PTX helpers
// ----------------------------------------------------------------------------
__device__ __forceinline__ void mma16816(float* c, const uint32_t* a,
                                         uint32_t b0, uint32_t b1) {
    asm volatile(
        "mma.sync.aligned.m16n8k16.row.col.f32.f16.f16.f32 "
        "{%0,%1,%2,%3}, {%4,%5,%6,%7}, {%8,%9}, {%0,%1,%2,%3};"
        : "+f"(c[0]), "+f"(c[1]), "+f"(c[2]), "+f"(c[3])
        : "r"(a[0]), "r"(a[1]), "r"(a[2]), "r"(a[3]), "r"(b0), "r"(b1));
}
__device__ __forceinline__ void ldsm4(uint32_t* r, uint32_t addr) {
    asm volatile("ldmatrix.sync.aligned.m8n8.x4.shared.b16 {%0,%1,%2,%3}, [%4];"
                 : "=r"(r[0]), "=r"(r[1]), "=r"(r[2]), "=r"(r[3]) : "r"(addr));
}
__device__ __forceinline__ void ldsm4t(uint32_t* r, uint32_t addr) {
    asm volatile("ldmatrix.sync.aligned.m8n8.x4.trans.shared.b16 {%0,%1,%2,%3}, [%4];"
                 : "=r"(r[0]), "=r"(r[1]), "=r"(r[2]), "=r"(r[3]) : "r"(addr));
}
__device__ __forceinline__ void cp16(uint32_t saddr, const void* g) {
    asm volatile("cp.async.cg.shared.global [%0], [%1], 16;" :: "r"(saddr), "l"(g));
}
__device__ __forceinline__ void cp_commit() {
    asm volatile("cp.async.commit_group;" ::: "memory");
}
__device__ __forceinline__ uint32_t scvta(const void* p) {
    return (uint32_t)__cvta_generic_to_shared(p);
}
__device__ __forceinline__ uint32_t pack_h2(float a, float b) {
    __half2 t = __floats2half2_rn(a, b);
    return *(uint32_t*)&t;
}

// ----------------------------------------------------------------------------
// RMSNorm: one block per row; writes fp16
// ----------------------------------------------------------------------------
__global__ void rmsnorm_kernel(const float* __restrict__ x,
                               const float* __restrict__ g,
                               __half* __restrict__ h) {
    const int s = blockIdx.x;
    const float2* xr = (const float2*)(x + (size_t)s * DMODEL);
    const float2* gr = (const float2*)g;
    float sum = 0.f;
    for (int d = threadIdx.x; d < DMODEL / 2; d += 256) {
        float2 v = xr[d];
        sum += v.x * v.x + v.y * v.y;
    }
    __shared__ float red[8];
    #pragma unroll
    for (int o = 16; o > 0; o >>= 1) sum += __shfl_xor_sync(0xffffffffu, sum, o);
    if ((threadIdx.x & 31) == 0) red[threadIdx.x >> 5] = sum;
    __syncthreads();
    if (threadIdx.x < 32) {
        float v = (threadIdx.x < 8) ? red[threadIdx.x] : 0.f;
        #pragma unroll
        for (int o = 4; o > 0; o >>= 1) v += __shfl_xor_sync(0xffffffffu, v, o);
        if (threadIdx.x == 0) red[0] = v;
    }
    __syncthreads();
    const float rinv = rsqrtf(red[0] / (float)DMODEL + 1e-9f);
    uint32_t* ph = (uint32_t*)(h + (size_t)s * DMODEL);
    for (int d = threadIdx.x; d < DMODEL / 2; d += 256) {
        const float2 v = xr[d];
        const float2 gg = gr[d];
        ph[d] = pack_h2(v.x * rinv * gg.x, v.y * rinv * gg.y);
    }
}

// ----------------------------------------------------------------------------
// Fused transpose of all 4 weights to fp16: W[K,N] fp32 -> Wt [N,K] fp16.
// Linear grid decoded: wq(4096) | wk(1024) | wv(1024) | wo(4096) blocks.
// ----------------------------------------------------------------------------
__global__ void transpose_all_kernel(const float* __restrict__ wq,
                                     const float* __restrict__ wk,
                                     const float* __restrict__ wv,
                                     const float* __restrict__ wo,
                                     __half* __restrict__ wqkvt,
                                     __half* __restrict__ wot) {
    const int bid = blockIdx.x;
    const float* src;
    __half* dst;
    int N, n0, k0;
    if (bid < 4096) {
        src = wq; dst = wqkvt; N = DMODEL;
        n0 = (bid & 63) * 32; k0 = (bid >> 6) * 32;
    } else if (bid < 5120) {
        const int b = bid - 4096;
        src = wk; dst = wqkvt + (size_t)DMODEL * DMODEL; N = KV_DIM;
        n0 = (b & 15) * 32; k0 = (b >> 4) * 32;
    } else if (bid < 6144) {
        const int b = bid - 5120;
        src = wv; dst = wqkvt + (size_t)(DMODEL + KV_DIM) * DMODEL; N = KV_DIM;
        n0 = (b & 15) * 32; k0 = (b >> 4) * 32;
    } else {
        const int b = bid - 6144;
        src = wo; dst = wot; N = DMODEL;
        n0 = (b & 63) * 32; k0 = (b >> 6) * 32;
    }
    const int K = DMODEL;   // all weights have K = DMODEL rows

    __shared__ float t[32][33];
    const int tx = threadIdx.x, ty = threadIdx.y;  // (32, 8)
    #pragma unroll
    for (int i = 0; i < 32; i += 8)
        t[ty + i][tx] = src[(size_t)(k0 + ty + i) * N + n0 + tx];
    __syncthreads();
    const int lt = ty * 32 + tx;
    const int n  = lt >> 3;
    const int kp = lt & 7;
    #pragma unroll
    for (int q = 0; q < 2; q++) {
        const int k2 = (kp + q * 8) * 2;
        const size_t o = (size_t)(n0 + n) * K + k0 + k2;
        *(uint32_t*)(dst + o) = pack_h2(t[k2][n], t[k2 + 1][n]);
    }
}

// ----------------------------------------------------------------------------
// fp16 GEMM: C[M,N] = A @ B^T (+Res if fp32 out), fp32 acc.
// Block 128x128, BK=32, 256 thr = 8 warps (2Mx4N), 4-stage cp.async,
// single barrier per mainloop iteration, 2 CTA/SM.
// ----------------------------------------------------------------------------
#define KP 40
#define NSTAGE 4
#define T_STG (128 * KP * 2)                 // 10240 bytes / array / stage
#define GEMM_SMEM (NSTAGE * 2 * T_STG)       // 81920

template<bool FP16OUT>
__global__ __launch_bounds__(256, 2) void mma_gemm_kernel(
    const __half* __restrict__ A, const __half* __restrict__ B,
    const float* __restrict__ Res, void* __restrict__ Cv,
    int N, int K) {
    extern __shared__ __align__(16) char sm[];
    const uint32_t smb = scvta(sm);
    const uint32_t oA = 0;
    const uint32_t oB = NSTAGE * T_STG;

    const int tid  = threadIdx.x;
    const int lane = tid & 31, wid = tid >> 5;
    const int bm = blockIdx.y * 128, bn = blockIdx.x * 128;
    const int wmb = (wid & 1) * 64;
    const int wnb = (wid >> 1) * 32;
    const int lr = lane >> 2, lc = (lane & 3) * 2;

    float acc[4][4][4];
    #pragma unroll
    for (int mt = 0; mt < 4; mt++)
        #pragma unroll
        for (int nt = 0; nt < 4; nt++)
            #pragma unroll
            for (int i = 0; i < 4; i++) acc[mt][nt][i] = 0.f;

    auto load_stage = [&](int s, int kc) {
        #pragma unroll
        for (int p = 0; p < 2; p++) {
            const int idx = tid + p * 256;
            const int r = idx >> 2, c8 = (idx & 3) * 8;
            const uint32_t off = (uint32_t)(r * KP + c8) * 2;
            cp16(smb + oA + s * T_STG + off, A + (size_t)(bm + r) * K + kc + c8);
            cp16(smb + oB + s * T_STG + off, B + (size_t)(bn + r) * K + kc + c8);
        }
    };

    const int nch = K >> 5;
    load_stage(0, 0);  cp_commit();
    load_stage(1, 32); cp_commit();
    load_stage(2, 64); cp_commit();

    const int a_row = lane & 15;
    const int a_kof = (lane >> 4) << 3;
    const int b_row = (lane & 7) + ((lane >> 4) << 3);
    const int b_kof = ((lane >> 3) & 1) << 3;

    for (int c = 0; c < nch; c++) {
        const int remaining = nch - 1 - c;
        if (remaining >= 2)      asm volatile("cp.async.wait_group 2;" ::: "memory");
        else if (remaining == 1) asm volatile("cp.async.wait_group 1;" ::: "memory");
        else                     asm volatile("cp.async.wait_group 0;" ::: "memory");
        __syncthreads();   // stage c visible; all warps done reading stage c-1
        if (c + NSTAGE - 1 < nch) {
            load_stage((c + 3) % NSTAGE, (c + 3) * 32);
            cp_commit();
        }
        const int cur = c % NSTAGE;
        const uint32_t sA = smb + oA + cur * T_STG;
        const uint32_t sB = smb + oB + cur * T_STG;

        #pragma unroll
        for (int kk = 0; kk < 32; kk += 16) {
            uint32_t fa[4][4];
            #pragma unroll
            for (int mt = 0; mt < 4; mt++) {
                const uint32_t off = (uint32_t)((wmb + mt * 16 + a_row) * KP + kk + a_kof) * 2;
                ldsm4(fa[mt], sA + off);
            }
            #pragma unroll
            for (int p2 = 0; p2 < 2; p2++) {
                const uint32_t off = (uint32_t)((wnb + p2 * 16 + b_row) * KP + kk + b_kof) * 2;
                uint32_t rb[4];
                ldsm4(rb, sB + off);
                #pragma unroll
                for (int mt = 0; mt < 4; mt++) {
                    mma16816(acc[mt][2 * p2],     fa[mt], rb[0], rb[1]);
                    mma16816(acc[mt][2 * p2 + 1], fa[mt], rb[2], rb[3]);
                }
            }
        }
    }

    #pragma unroll
    for (int mt = 0; mt < 4; mt++) {
        const int row0 = bm + wmb + mt * 16 + lr;
        #pragma unroll
        for (int nt = 0; nt < 4; nt++) {
            const int col = bn + wnb + nt * 8 + lc;
            if constexpr (FP16OUT) {
                __half* C = (__half*)Cv;
                *(uint32_t*)(C + (size_t)row0 * N + col) =
                    pack_h2(acc[mt][nt][0], acc[mt][nt][1]);
                *(uint32_t*)(C + (size_t)(row0 + 8) * N + col) =
                    pack_h2(acc[mt][nt][2], acc[mt][nt][3]);
            } else {
                float* C = (float*)Cv;
                float2 v0 = make_float2(acc[mt][nt][0], acc[mt][nt][1]);
                float2 v1 = make_float2(acc[mt][nt][2], acc[mt][nt][3]);
                if (Res) {
                    const float2 q0 = *(const float2*)(Res + (size_t)row0 * N + col);
                    const float2 q1 = *(const float2*)(Res + (size_t)(row0 + 8) * N + col);
                    v0.x += q0.x; v0.y += q0.y;
                    v1.x += q1.x; v1.y += q1.y;
                }
                *(float2*)(C + (size_t)row0 * N + col) = v0;
                *(float2*)(C + (size_t)(row0 + 8) * N + col) = v1;
            }
        }
    }
}

// ----------------------------------------------------------------------------
// RoPE + scale, fp16 in -> fp16 out
// ----------------------------------------------------------------------------
__global__ void rope_half_kernel(const __half* __restrict__ src, int src_stride,
                                 __half* __restrict__ oh,
                                 int o_stride, int H, float scale, int total) {
    int idx = blockIdx.x * blockDim.x + threadIdx.x;
    if (idx >= total) return;
    const int i2 = idx & 15;
    const int h = (idx >> 4) % H;
    const int s = idx / (16 * H);
    const __half* p = src + (size_t)s * src_stride + h * HD;
    float y[4];
    #pragma unroll
    for (int q = 0; q < 2; q++) {
        const int i = 2 * i2 + q;
        const double inv = pow(10000.0, -(double)(2 * i) / (double)HD);
        const double ang = (double)s * inv;
        const float cs = (float)cos(ang);
        const float sn = (float)sin(ang);
        const float x1 = __half2float(p[i]), x2 = __half2float(p[i + 32]);
        y[q]     = (x1 * cs - x2 * sn) * scale;
        y[2 + q] = (x1 * sn + x2 * cs) * scale;
    }
    __half* ph = oh + (size_t)s * o_stride + h * HD;
    *(uint32_t*)(ph + 2 * i2)      = pack_h2(y[0], y[1]);
    *(uint32_t*)(ph + 2 * i2 + 32) = pack_h2(y[2], y[3]);
}

// ----------------------------------------------------------------------------
// Tensor-core causal GQA flash attention (fp16).
// Grid (S/128, HQ). 256 threads = 8 warps x 16 q-rows, 2 CTAs/SM.
// KV tiles of 64, 3-stage cp.async pipeline, ONE barrier per kv tile.
// V read strided from pqkv. Dynamic smem: 3 * KV_STG.
// ----------------------------------------------------------------------------
#define AQP 72
#define KV_STG 18432                 // bytes per stage (K 9216 + V 9216)
#define ATTN_SMEM (3 * KV_STG)       // 55296

__global__ __launch_bounds__(256, 2) void attn_mma_kernel(
    const __half* __restrict__ qg, const __half* __restrict__ kg,
    const __half* __restrict__ vg, int vstride, __half* __restrict__ og) {
    extern __shared__ __align__(16) char sbuf[];
    const uint32_t smb = scvta(sbuf);
    __half* QH = (__half*)sbuf;                 // [128][72] staging (stage-0 reuse)

    const int qt = blockIdx.x, h = blockIdx.y;
    const int kvh = h >> 2;
    const int tid = threadIdx.x, lane = tid & 31, wid = tid >> 5;
    const int lr = lane >> 2, lc = (lane & 3) * 2;

    // ---- stage Q (128 rows x 64 halves = 1024 chunks of 8 halves) ----
    #pragma unroll
    for (int p = 0; p < 4; p++) {
        const int idx = tid + p * 256;
        const int r = idx >> 3, c8 = (idx & 7) * 8;
        const size_t go = (size_t)(qt * 128 + r) * DMODEL + h * HD + c8;
        *(uint4*)(QH + r * AQP + c8) = *(const uint4*)(qg + go);
    }
    __syncthreads();

    uint32_t qf[4][4];
    {
        const int a_row = lane & 15;
        const int a_kof = (lane >> 4) << 3;
        #pragma unroll
        for (int ks = 0; ks < 4; ks++) {
            const uint32_t off = (uint32_t)((wid * 16 + a_row) * AQP + ks * 16 + a_kof) * 2;
            ldsm4(qf[ks], smb + off);
        }
    }
    __syncthreads();   // Q frags in regs; smem free for KV stages

    float o[8][4];
    #pragma unroll
    for (int n = 0; n < 8; n++)
        #pragma unroll
        for (int i = 0; i < 4; i++) o[n][i] = 0.f;
    float m0 = -1e30f, m1 = -1e30f, l0 = 0.f, l1 = 0.f;

    const int row0g = qt * 128 + wid * 16 + lr;
    const int row1g = row0g + 8;
    const int nkt = 2 * qt + 2;

    const int b_row = (lane & 7) + ((lane >> 4) << 3);
    const int b_kof = ((lane >> 3) & 1) << 3;
    const int v_row = lane & 15;
    const int v_col = (lane >> 4) << 3;

    auto load_kv = [&](int stage, int kt) {
        const uint32_t base = smb + stage * KV_STG;
        #pragma unroll
        for (int p = 0; p < 2; p++) {
            const int idx = tid + p * 256;
            const int r = idx >> 3, c8 = (idx & 7) * 8;
            const uint32_t off = (uint32_t)(r * AQP + c8) * 2;
            cp16(base + off,
                 kg + (size_t)(kt * 64 + r) * KV_DIM + kvh * HD + c8);
            cp16(base + 9216 + off,
                 vg + (size_t)(kt * 64 + r) * vstride + kvh * HD + c8);
        }
    };

    load_kv(0, 0);
    cp_commit();
    load_kv(1, 1);      // nkt >= 2 always
    cp_commit();

    for (int kt = 0; kt < nkt; kt++) {
        if (kt + 1 < nkt) asm volatile("cp.async.wait_group 1;" ::: "memory");
        else              asm volatile("cp.async.wait_group 0;" ::: "memory");
        __syncthreads();  // stage kt%3 ready; all warps past iter kt-1 reads
        if (kt + 2 < nkt) {
            load_kv((kt + 2) % 3, kt + 2);
            cp_commit();
        }
        const uint32_t sK = smb + (kt % 3) * KV_STG;
        const uint32_t sV = sK + 9216;

        // ---- S = Q K^T ----
        float s[8][4];
        #pragma unroll
        for (int n = 0; n < 8; n++)
            #pragma unroll
            for (int i = 0; i < 4; i++) s[n][i] = 0.f;
        #pragma unroll
        for (int ks = 0; ks < 4; ks++) {
            #pragma unroll
            for (int p2 = 0; p2 < 4; p2++) {
                const uint32_t off = (uint32_t)((p2 * 16 + b_row) * AQP + ks * 16 + b_kof) * 2;
                uint32_t rk[4];
                ldsm4(rk, sK + off);
                mma16816(s[2 * p2],     qf[ks], rk[0], rk[1]);
                mma16816(s[2 * p2 + 1], qf[ks], rk[2], rk[3]);
            }
        }

        // ---- causal mask ----
        if (kt >= 2 * qt) {
            #pragma unroll
            for (int n = 0; n < 8; n++) {
                const int colb = kt * 64 + n * 8 + lc;
                if (colb     > row0g) s[n][0] = -1e30f;
                if (colb + 1 > row0g) s[n][1] = -1e30f;
                if (colb     > row1g) s[n][2] = -1e30f;
                if (colb + 1 > row1g) s[n][3] = -1e30f;
            }
        }

        // ---- online softmax ----
        float tm0 = -1e30f, tm1 = -1e30f;
        #pragma unroll
        for (int n = 0; n < 8; n++) {
            tm0 = fmaxf(tm0, fmaxf(s[n][0], s[n][1]));
            tm1 = fmaxf(tm1, fmaxf(s[n][2], s[n][3]));
        }
        tm0 = fmaxf(tm0, __shfl_xor_sync(0xffffffffu, tm0, 1));
        tm0 = fmaxf(tm0, __shfl_xor_sync(0xffffffffu, tm0, 2));
        tm1 = fmaxf(tm1, __shfl_xor_sync(0xffffffffu, tm1, 1));
        tm1 = fmaxf(tm1, __shfl_xor_sync(0xffffffffu, tm1, 2));
        const float mn0 = fmaxf(m0, tm0), mn1 = fmaxf(m1, tm1);
        const float a0 = __expf(m0 - mn0), a1 = __expf(m1 - mn1);
        m0 = mn0; m1 = mn1;

        uint32_t pA[8], pB[8];
        float rs0 = 0.f, rs1 = 0.f;
        #pragma unroll
        for (int n = 0; n < 8; n++) {
            const float p0 = __expf(s[n][0] - m0);
            const float p1 = __expf(s[n][1] - m0);
            const float p2 = __expf(s[n][2] - m1);
            const float p3 = __expf(s[n][3] - m1);
            rs0 += p0 + p1; rs1 += p2 + p3;
            pA[n] = pack_h2(p0, p1);
            pB[n] = pack_h2(p2, p3);
        }
        rs0 += __shfl_xor_sync(0xffffffffu, rs0, 1);
        rs0 += __shfl_xor_sync(0xffffffffu, rs0, 2);
        rs1 += __shfl_xor_sync(0xffffffffu, rs1, 1);
        rs1 += __shfl_xor_sync(0xffffffffu, rs1, 2);
        l0 = l0 * a0 + rs0;
        l1 = l1 * a1 + rs1;
        #pragma unroll
        for (int n = 0; n < 8; n++) {
            o[n][0] *= a0; o[n][1] *= a0;
            o[n][2] *= a1; o[n][3] *= a1;
        }

        // ---- O += P V ----
        #pragma unroll
        for (int j = 0; j < 4; j++) {
            uint32_t aP[4] = {pA[2*j], pB[2*j], pA[2*j+1], pB[2*j+1]};
            #pragma unroll
            for (int p2 = 0; p2 < 4; p2++) {
                const uint32_t off =
                    (uint32_t)((j * 16 + v_row) * AQP + p2 * 16 + v_col) * 2;
                uint32_t rv[4];
                ldsm4t(rv, sV + off);
                mma16816(o[2 * p2],     aP, rv[0], rv[1]);
                mma16816(o[2 * p2 + 1], aP, rv[2], rv[3]);
            }
        }
        // no trailing barrier: 3-stage ring + top-of-loop barrier protect reuse
    }

    // ---- epilogue ----
    const float i0 = 1.f / l0, i1 = 1.f / l1;
    #pragma unroll
    for (int n = 0; n < 8; n++) {
        const int col = h * HD + n * 8 + lc;
        *(uint32_t*)(og + (size_t)row0g * DMODEL + col) =
            pack_h2(o[n][0] * i0, o[n][1] * i0);
        *(uint32_t*)(og + (size_t)row1g * DMODEL + col) =
            pack_h2(o[n][2] * i1, o[n][3] * i1);
    }
}

// ----------------------------------------------------------------------------
// Launch
// ----------------------------------------------------------------------------
extern "C" void kernel_launch(void* const* d_in, const int* in_sizes, int n_in,
                              void* d_out, int out_size) {
    const float* x  = (const float*)d_in[0];
    const float* g  = (const float*)d_in[1];
    const float* wq = (const float*)d_in[2];
    const float* wk = (const float*)d_in[3];
    const float* wv = (const float*)d_in[4];
    const float* wo = (const float*)d_in[5];
    float* out = (float*)d_out;

    static bool inited = false;
    static __half *hh, *wqkvt, *wot, *pqkv, *q16, *k16, *o16;
    if (!inited) {
        inited = true;
        cudaFuncSetAttribute(mma_gemm_kernel<true>,
                             cudaFuncAttributeMaxDynamicSharedMemorySize, GEMM_SMEM);
        cudaFuncSetAttribute(mma_gemm_kernel<false>,
                             cudaFuncAttributeMaxDynamicSharedMemorySize, GEMM_SMEM);
        cudaFuncSetAttribute(attn_mma_kernel,
                             cudaFuncAttributeMaxDynamicSharedMemorySize, ATTN_SMEM);
        cudaGetSymbolAddress((void**)&hh,    g_h);
        cudaGetSymbolAddress((void**)&wqkvt, g_wqkvt);
        cudaGetSymbolAddress((void**)&wot,   g_wot);
        cudaGetSymbolAddress((void**)&pqkv,  g_pqkv);
        cudaGetSymbolAddress((void**)&q16,   g_q);
        cudaGetSymbolAddress((void**)&k16,   g_k);
        cudaGetSymbolAddress((void**)&o16,   g_o);
    }

    // 1) RMSNorm -> fp16
    rmsnorm_kernel<<<S_LEN, 256>>>(x, g, hh);

    // 2) All weight transposes in ONE launch
    transpose_all_kernel<<<10240, dim3(32, 8)>>>(wq, wk, wv, wo, wqkvt, wot);

    // 3) Fused QKV projection (fp16 out)
    mma_gemm_kernel<true><<<dim3(QKV_N / 128, S_LEN / 128), 256, GEMM_SMEM>>>(
        hh, wqkvt, nullptr, pqkv, QKV_N, DMODEL);

    // 4) RoPE (q scaled by 1/sqrt(HD)); V used in place from pqkv
    {
        const int tq = S_LEN * HQ * 16;
        rope_half_kernel<<<(tq + 255) / 256, 256>>>(pqkv, QKV_N, q16, DMODEL, HQ, 0.125f, tq);
        const int tk = S_LEN * HKV * 16;
        rope_half_kernel<<<(tk + 255) / 256, 256>>>(pqkv + DMODEL, QKV_N, k16, KV_DIM, HKV, 1.0f, tk);
    }

    // 5) Attention (V strided directly out of pqkv) — launch #6 for ncu -s 5
    attn_mma_kernel<<<dim3(S_LEN / 128, HQ), 256, ATTN_SMEM>>>(
        q16, k16, pqkv + DMODEL + KV_DIM, QKV_N, o16);

    // 6) Output projection + residual (fp32 out)
    mma_gemm_kernel<false><<<dim3(DMODEL / 128, S_LEN / 128), 256, GEMM_SMEM>>>(
        o16, wot, x, out, DMODEL, DMODEL);
}

// round 17
// speedup vs baseline: 2.9576x; 2.9576x over previous
#include <cuda_runtime.h>
#include <cuda_fp16.h>
#include <cstdint>
#include <math.h>

// ----------------------------------------------------------------------------
// Problem constants
// ----------------------------------------------------------------------------
#define S_LEN   2048
#define DMODEL  2048
#define HQ      32
#define HKV     8
#define HD      64
#define KV_DIM  (HKV*HD)   // 512
#define QKV_N   (DMODEL + 2 * KV_DIM)   // 3072

// ----------------------------------------------------------------------------
// Scratch (static __device__ arrays: allocation-free)
// ----------------------------------------------------------------------------
__device__ __half g_h[S_LEN * DMODEL];            // rmsnorm out fp16
__device__ __half g_wqkvt[QKV_N * DMODEL];        // [wq^T; wk^T; wv^T] fp16 [N,K]
__device__ __half g_wot[DMODEL * DMODEL];
__device__ __half g_pqkv[S_LEN * QKV_N];          // fused projection out (fp16)
__device__ __half g_q[S_LEN * DMODEL];            // roped+scaled q
__device__ __half g_k[S_LEN * KV_DIM];            // roped k
__device__ __half g_o[S_LEN * DMODEL];            // attn out
__device__ float2 g_rope_tab[S_LEN * 32];         // (cos, sin) per (s, dim-pair)

// ----------------------------------------------------------------------------
// PTX helpers
// ----------------------------------------------------------------------------
__device__ __forceinline__ void mma16816(float* c, const uint32_t* a,
                                         uint32_t b0, uint32_t b1) {
    asm volatile(
        "mma.sync.aligned.m16n8k16.row.col.f32.f16.f16.f32 "
        "{%0,%1,%2,%3}, {%4,%5,%6,%7}, {%8,%9}, {%0,%1,%2,%3};"
        : "+f"(c[0]), "+f"(c[1]), "+f"(c[2]), "+f"(c[3])
        : "r"(a[0]), "r"(a[1]), "r"(a[2]), "r"(a[3]), "r"(b0), "r"(b1));
}
__device__ __forceinline__ void ldsm4(uint32_t* r, uint32_t addr) {
    asm volatile("ldmatrix.sync.aligned.m8n8.x4.shared.b16 {%0,%1,%2,%3}, [%4];"
                 : "=r"(r[0]), "=r"(r[1]), "=r"(r[2]), "=r"(r[3]) : "r"(addr));
}
__device__ __forceinline__ void ldsm4t(uint32_t* r, uint32_t addr) {
    asm volatile("ldmatrix.sync.aligned.m8n8.x4.trans.shared.b16 {%0,%1,%2,%3}, [%4];"
                 : "=r"(r[0]), "=r"(r[1]), "=r"(r[2]), "=r"(r[3]) : "r"(addr));
}
__device__ __forceinline__ void cp16(uint32_t saddr, const void* g) {
    asm volatile("cp.async.cg.shared.global [%0], [%1], 16;" :: "r"(saddr), "l"(g));
}
__device__ __forceinline__ void cp_commit() {
    asm volatile("cp.async.commit_group;" ::: "memory");
}
__device__ __forceinline__ uint32_t scvta(const void* p) {
    return (uint32_t)__cvta_generic_to_shared(p);
}
__device__ __forceinline__ uint32_t pack_h2(float a, float b) {
    __half2 t = __floats2half2_rn(a, b);
    return *(uint32_t*)&t;
}

// ----------------------------------------------------------------------------
// RoPE table: (cos, sin) for all (s, i) pairs. fp64 math paid ONCE (65K thr).
// ----------------------------------------------------------------------------
__global__ void rope_table_kernel(float2* __restrict__ tab) {
    const int idx = blockIdx.x * blockDim.x + threadIdx.x;
    if (idx >= S_LEN * 32) return;
    const int s = idx >> 5, i = idx & 31;
    const double inv = pow(10000.0, -(double)(2 * i) / (double)HD);
    const double ang = (double)s * inv;
    tab[idx] = make_float2((float)cos(ang), (float)sin(ang));
}

// ----------------------------------------------------------------------------
// RMSNorm: one block per row; writes fp16
// ----------------------------------------------------------------------------
__global__ void rmsnorm_kernel(const float* __restrict__ x,
                               const float* __restrict__ g,
                               __half* __restrict__ h) {
    const int s = blockIdx.x;
    const float2* xr = (const float2*)(x + (size_t)s * DMODEL);
    const float2* gr = (const float2*)g;
    float sum = 0.f;
    for (int d = threadIdx.x; d < DMODEL / 2; d += 256) {
        float2 v = xr[d];
        sum += v.x * v.x + v.y * v.y;
    }
    __shared__ float red[8];
    #pragma unroll
    for (int o = 16; o > 0; o >>= 1) sum += __shfl_xor_sync(0xffffffffu, sum, o);
    if ((threadIdx.x & 31) == 0) red[threadIdx.x >> 5] = sum;
    __syncthreads();
    if (threadIdx.x < 32) {
        float v = (threadIdx.x < 8) ? red[threadIdx.x] : 0.f;
        #pragma unroll
        for (int o = 4; o > 0; o >>= 1) v += __shfl_xor_sync(0xffffffffu, v, o);
        if (threadIdx.x == 0) red[0] = v;
    }
    __syncthreads();
    const float rinv = rsqrtf(red[0] / (float)DMODEL + 1e-9f);
    uint32_t* ph = (uint32_t*)(h + (size_t)s * DMODEL);
    for (int d = threadIdx.x; d < DMODEL / 2; d += 256) {
        const float2 v = xr[d];
        const float2 gg = gr[d];
        ph[d] = pack_h2(v.x * rinv * gg.x, v.y * rinv * gg.y);
    }
}

// ----------------------------------------------------------------------------
// Fused transpose of all 4 weights to fp16: W[K,N] fp32 -> Wt [N,K] fp16.
// ----------------------------------------------------------------------------
__global__ void transpose_all_kernel(const float* __restrict__ wq,
                                     const float* __restrict__ wk,
                                     const float* __restrict__ wv,
                                     const float* __restrict__ wo,
                                     __half* __restrict__ wqkvt,
                                     __half* __restrict__ wot) {
    const int bid = blockIdx.x;
    const float* src;
    __half* dst;
    int N, n0, k0;
    if (bid < 4096) {
        src = wq; dst = wqkvt; N = DMODEL;
        n0 = (bid & 63) * 32; k0 = (bid >> 6) * 32;
    } else if (bid < 5120) {
        const int b = bid - 4096;
        src = wk; dst = wqkvt + (size_t)DMODEL * DMODEL; N = KV_DIM;
        n0 = (b & 15) * 32; k0 = (b >> 4) * 32;
    } else if (bid < 6144) {
        const int b = bid - 5120;
        src = wv; dst = wqkvt + (size_t)(DMODEL + KV_DIM) * DMODEL; N = KV_DIM;
        n0 = (b & 15) * 32; k0 = (b >> 4) * 32;
    } else {
        const int b = bid - 6144;
        src = wo; dst = wot; N = DMODEL;
        n0 = (b & 63) * 32; k0 = (b >> 6) * 32;
    }
    const int K = DMODEL;

    __shared__ float t[32][33];
    const int tx = threadIdx.x, ty = threadIdx.y;  // (32, 8)
    #pragma unroll
    for (int i = 0; i < 32; i += 8)
        t[ty + i][tx] = src[(size_t)(k0 + ty + i) * N + n0 + tx];
    __syncthreads();
    const int lt = ty * 32 + tx;
    const int n  = lt >> 3;
    const int kp = lt & 7;
    #pragma unroll
    for (int q = 0; q < 2; q++) {
        const int k2 = (kp + q * 8) * 2;
        const size_t o = (size_t)(n0 + n) * K + k0 + k2;
        *(uint32_t*)(dst + o) = pack_h2(t[k2][n], t[k2 + 1][n]);
    }
}

// ----------------------------------------------------------------------------
// fp16 GEMM: C[M,N] = A @ B^T (+Res if fp32 out), fp32 acc.
// Block 128x128, BK=32, 8 warps (2Mx4N), 4-stage cp.async, 2 CTA/SM.
// ----------------------------------------------------------------------------
#define KP 40
#define NSTAGE 4
#define T_STG (128 * KP * 2)                 // 10240 bytes / array / stage
#define GEMM_SMEM (NSTAGE * 2 * T_STG)       // 81920

template<bool FP16OUT>
__global__ __launch_bounds__(256, 2) void mma_gemm_kernel(
    const __half* __restrict__ A, const __half* __restrict__ B,
    const float* __restrict__ Res, void* __restrict__ Cv,
    int N, int K) {
    extern __shared__ __align__(16) char sm[];
    const uint32_t smb = scvta(sm);
    const uint32_t oA = 0;
    const uint32_t oB = NSTAGE * T_STG;

    const int tid  = threadIdx.x;
    const int lane = tid & 31, wid = tid >> 5;
    const int bm = blockIdx.y * 128, bn = blockIdx.x * 128;
    const int wmb = (wid & 1) * 64;
    const int wnb = (wid >> 1) * 32;
    const int lr = lane >> 2, lc = (lane & 3) * 2;

    float acc[4][4][4];
    #pragma unroll
    for (int mt = 0; mt < 4; mt++)
        #pragma unroll
        for (int nt = 0; nt < 4; nt++)
            #pragma unroll
            for (int i = 0; i < 4; i++) acc[mt][nt][i] = 0.f;

    auto load_stage = [&](int s, int kc) {
        #pragma unroll
        for (int p = 0; p < 2; p++) {
            const int idx = tid + p * 256;
            const int r = idx >> 2, c8 = (idx & 3) * 8;
            const uint32_t off = (uint32_t)(r * KP + c8) * 2;
            cp16(smb + oA + s * T_STG + off, A + (size_t)(bm + r) * K + kc + c8);
            cp16(smb + oB + s * T_STG + off, B + (size_t)(bn + r) * K + kc + c8);
        }
    };

    const int nch = K >> 5;
    load_stage(0, 0);  cp_commit();
    load_stage(1, 32); cp_commit();
    load_stage(2, 64); cp_commit();

    const int a_row = lane & 15;
    const int a_kof = (lane >> 4) << 3;
    const int b_row = (lane & 7) + ((lane >> 4) << 3);
    const int b_kof = ((lane >> 3) & 1) << 3;

    for (int c = 0; c < nch; c++) {
        const int remaining = nch - 1 - c;
        if (remaining >= 2)      asm volatile("cp.async.wait_group 2;" ::: "memory");
        else if (remaining == 1) asm volatile("cp.async.wait_group 1;" ::: "memory");
        else                     asm volatile("cp.async.wait_group 0;" ::: "memory");
        __syncthreads();
        if (c + NSTAGE - 1 < nch) {
            load_stage((c + 3) % NSTAGE, (c + 3) * 32);
            cp_commit();
        }
        const int cur = c % NSTAGE;
        const uint32_t sA = smb + oA + cur * T_STG;
        const uint32_t sB = smb + oB + cur * T_STG;

        #pragma unroll
        for (int kk = 0; kk < 32; kk += 16) {
            uint32_t fa[4][4];
            #pragma unroll
            for (int mt = 0; mt < 4; mt++) {
                const uint32_t off = (uint32_t)((wmb + mt * 16 + a_row) * KP + kk + a_kof) * 2;
                ldsm4(fa[mt], sA + off);
            }
            #pragma unroll
            for (int p2 = 0; p2 < 2; p2++) {
                const uint32_t off = (uint32_t)((wnb + p2 * 16 + b_row) * KP + kk + b_kof) * 2;
                uint32_t rb[4];
                ldsm4(rb, sB + off);
                #pragma unroll
                for (int mt = 0; mt < 4; mt++) {
                    mma16816(acc[mt][2 * p2],     fa[mt], rb[0], rb[1]);
                    mma16816(acc[mt][2 * p2 + 1], fa[mt], rb[2], rb[3]);
                }
            }
        }
    }

    #pragma unroll
    for (int mt = 0; mt < 4; mt++) {
        const int row0 = bm + wmb + mt * 16 + lr;
        #pragma unroll
        for (int nt = 0; nt < 4; nt++) {
            const int col = bn + wnb + nt * 8 + lc;
            if constexpr (FP16OUT) {
                __half* C = (__half*)Cv;
                *(uint32_t*)(C + (size_t)row0 * N + col) =
                    pack_h2(acc[mt][nt][0], acc[mt][nt][1]);
                *(uint32_t*)(C + (size_t)(row0 + 8) * N + col) =
                    pack_h2(acc[mt][nt][2], acc[mt][nt][3]);
            } else {
                float* C = (float*)Cv;
                float2 v0 = make_float2(acc[mt][nt][0], acc[mt][nt][1]);
                float2 v1 = make_float2(acc[mt][nt][2], acc[mt][nt][3]);
                if (Res) {
                    const float2 q0 = *(const float2*)(Res + (size_t)row0 * N + col);
                    const float2 q1 = *(const float2*)(Res + (size_t)(row0 + 8) * N + col);
                    v0.x += q0.x; v0.y += q0.y;
                    v1.x += q1.x; v1.y += q1.y;
                }
                *(float2*)(C + (size_t)row0 * N + col) = v0;
                *(float2*)(C + (size_t)(row0 + 8) * N + col) = v1;
            }
        }
    }
}

// ----------------------------------------------------------------------------
// RoPE + scale via precomputed table, fp16 in -> fp16 out
// ----------------------------------------------------------------------------
__global__ void rope_half_kernel(const __half* __restrict__ src, int src_stride,
                                 __half* __restrict__ oh,
                                 int o_stride, int H, float scale, int total,
                                 const float2* __restrict__ tab) {
    int idx = blockIdx.x * blockDim.x + threadIdx.x;
    if (idx >= total) return;
    const int i2 = idx & 15;
    const int h = (idx >> 4) % H;
    const int s = idx / (16 * H);
    const __half* p = src + (size_t)s * src_stride + h * HD;
    float y[4];
    #pragma unroll
    for (int q = 0; q < 2; q++) {
        const int i = 2 * i2 + q;
        const float2 cs = tab[s * 32 + i];
        const float x1 = __half2float(p[i]), x2 = __half2float(p[i + 32]);
        y[q]     = (x1 * cs.x - x2 * cs.y) * scale;
        y[2 + q] = (x1 * cs.y + x2 * cs.x) * scale;
    }
    __half* ph = oh + (size_t)s * o_stride + h * HD;
    *(uint32_t*)(ph + 2 * i2)      = pack_h2(y[0], y[1]);
    *(uint32_t*)(ph + 2 * i2 + 32) = pack_h2(y[2], y[3]);
}

// ----------------------------------------------------------------------------
// Tensor-core causal GQA flash attention (fp16).
// Grid (S/128, HQ). 8 warps x 16 q-rows, 2 CTAs/SM.
// KV tiles of 64, 3-stage cp.async, one barrier per kv tile.
// ----------------------------------------------------------------------------
#define AQP 72
#define KV_STG 18432                 // bytes per stage (K 9216 + V 9216)
#define ATTN_SMEM (3 * KV_STG)       // 55296

__global__ __launch_bounds__(256, 2) void attn_mma_kernel(
    const __half* __restrict__ qg, const __half* __restrict__ kg,
    const __half* __restrict__ vg, int vstride, __half* __restrict__ og) {
    extern __shared__ __align__(16) char sbuf[];
    const uint32_t smb = scvta(sbuf);
    __half* QH = (__half*)sbuf;

    const int qt = blockIdx.x, h = blockIdx.y;
    const int kvh = h >> 2;
    const int tid = threadIdx.x, lane = tid & 31, wid = tid >> 5;
    const int lr = lane >> 2, lc = (lane & 3) * 2;

    // ---- stage Q ----
    #pragma unroll
    for (int p = 0; p < 4; p++) {
        const int idx = tid + p * 256;
        const int r = idx >> 3, c8 = (idx & 7) * 8;
        const size_t go = (size_t)(qt * 128 + r) * DMODEL + h * HD + c8;
        *(uint4*)(QH + r * AQP + c8) = *(const uint4*)(qg + go);
    }
    __syncthreads();

    uint32_t qf[4][4];
    {
        const int a_row = lane & 15;
        const int a_kof = (lane >> 4) << 3;
        #pragma unroll
        for (int ks = 0; ks < 4; ks++) {
            const uint32_t off = (uint32_t)((wid * 16 + a_row) * AQP + ks * 16 + a_kof) * 2;
            ldsm4(qf[ks], smb + off);
        }
    }
    __syncthreads();

    float o[8][4];
    #pragma unroll
    for (int n = 0; n < 8; n++)
        #pragma unroll
        for (int i = 0; i < 4; i++) o[n][i] = 0.f;
    float m0 = -1e30f, m1 = -1e30f, l0 = 0.f, l1 = 0.f;

    const int row0g = qt * 128 + wid * 16 + lr;
    const int row1g = row0g + 8;
    const int nkt = 2 * qt + 2;

    const int b_row = (lane & 7) + ((lane >> 4) << 3);
    const int b_kof = ((lane >> 3) & 1) << 3;
    const int v_row = lane & 15;
    const int v_col = (lane >> 4) << 3;

    auto load_kv = [&](int stage, int kt) {
        const uint32_t base = smb + stage * KV_STG;
        #pragma unroll
        for (int p = 0; p < 2; p++) {
            const int idx = tid + p * 256;
            const int r = idx >> 3, c8 = (idx & 7) * 8;
            const uint32_t off = (uint32_t)(r * AQP + c8) * 2;
            cp16(base + off,
                 kg + (size_t)(kt * 64 + r) * KV_DIM + kvh * HD + c8);
            cp16(base + 9216 + off,
                 vg + (size_t)(kt * 64 + r) * vstride + kvh * HD + c8);
        }
    };

    load_kv(0, 0);
    cp_commit();
    load_kv(1, 1);
    cp_commit();

    for (int kt = 0; kt < nkt; kt++) {
        if (kt + 1 < nkt) asm volatile("cp.async.wait_group 1;" ::: "memory");
        else              asm volatile("cp.async.wait_group 0;" ::: "memory");
        __syncthreads();
        if (kt + 2 < nkt) {
            load_kv((kt + 2) % 3, kt + 2);
            cp_commit();
        }
        const uint32_t sK = smb + (kt % 3) * KV_STG;
        const uint32_t sV = sK + 9216;

        // ---- S = Q K^T ----
        float s[8][4];
        #pragma unroll
        for (int n = 0; n < 8; n++)
            #pragma unroll
            for (int i = 0; i < 4; i++) s[n][i] = 0.f;
        #pragma unroll
        for (int ks = 0; ks < 4; ks++) {
            #pragma unroll
            for (int p2 = 0; p2 < 4; p2++) {
                const uint32_t off = (uint32_t)((p2 * 16 + b_row) * AQP + ks * 16 + b_kof) * 2;
                uint32_t rk[4];
                ldsm4(rk, sK + off);
                mma16816(s[2 * p2],     qf[ks], rk[0], rk[1]);
                mma16816(s[2 * p2 + 1], qf[ks], rk[2], rk[3]);
            }
        }

        // ---- causal mask ----
        if (kt >= 2 * qt) {
            #pragma unroll
            for (int n = 0; n < 8; n++) {
                const int colb = kt * 64 + n * 8 + lc;
                if (colb     > row0g) s[n][0] = -1e30f;
                if (colb + 1 > row0g) s[n][1] = -1e30f;
                if (colb     > row1g) s[n][2] = -1e30f;
                if (colb + 1 > row1g) s[n][3] = -1e30f;
            }
        }

        // ---- online softmax ----
        float tm0 = -1e30f, tm1 = -1e30f;
        #pragma unroll
        for (int n = 0; n < 8; n++) {
            tm0 = fmaxf(tm0, fmaxf(s[n][0], s[n][1]));
            tm1 = fmaxf(tm1, fmaxf(s[n][2], s[n][3]));
        }
        tm0 = fmaxf(tm0, __shfl_xor_sync(0xffffffffu, tm0, 1));
        tm0 = fmaxf(tm0, __shfl_xor_sync(0xffffffffu, tm0, 2));
        tm1 = fmaxf(tm1, __shfl_xor_sync(0xffffffffu, tm1, 1));
        tm1 = fmaxf(tm1, __shfl_xor_sync(0xffffffffu, tm1, 2));
        const float mn0 = fmaxf(m0, tm0), mn1 = fmaxf(m1, tm1);
        const float a0 = __expf(m0 - mn0), a1 = __expf(m1 - mn1);
        m0 = mn0; m1 = mn1;

        uint32_t pA[8], pB[8];
        float rs0 = 0.f, rs1 = 0.f;
        #pragma unroll
        for (int n = 0; n < 8; n++) {
            const float p0 = __expf(s[n][0] - m0);
            const float p1 = __expf(s[n][1] - m0);
            const float p2 = __expf(s[n][2] - m1);
            const float p3 = __expf(s[n][3] - m1);
            rs0 += p0 + p1; rs1 += p2 + p3;
            pA[n] = pack_h2(p0, p1);
            pB[n] = pack_h2(p2, p3);
        }
        rs0 += __shfl_xor_sync(0xffffffffu, rs0, 1);
        rs0 += __shfl_xor_sync(0xffffffffu, rs0, 2);
        rs1 += __shfl_xor_sync(0xffffffffu, rs1, 1);
        rs1 += __shfl_xor_sync(0xffffffffu, rs1, 2);
        l0 = l0 * a0 + rs0;
        l1 = l1 * a1 + rs1;
        #pragma unroll
        for (int n = 0; n < 8; n++) {
            o[n][0] *= a0; o[n][1] *= a0;
            o[n][2] *= a1; o[n][3] *= a1;
        }

        // ---- O += P V ----
        #pragma unroll
        for (int j = 0; j < 4; j++) {
            uint32_t aP[4] = {pA[2*j], pB[2*j], pA[2*j+1], pB[2*j+1]};
            #pragma unroll
            for (int p2 = 0; p2 < 4; p2++) {
                const uint32_t off =
                    (uint32_t)((j * 16 + v_row) * AQP + p2 * 16 + v_col) * 2;
                uint32_t rv[4];
                ldsm4t(rv, sV + off);
                mma16816(o[2 * p2],     aP, rv[0], rv[1]);
                mma16816(o[2 * p2 + 1], aP, rv[2], rv[3]);
            }
        }
    }

    // ---- epilogue ----
    const float i0 = 1.f / l0, i1 = 1.f / l1;
    #pragma unroll
    for (int n = 0; n < 8; n++) {
        const int col = h * HD + n * 8 + lc;
        *(uint32_t*)(og + (size_t)row0g * DMODEL + col) =
            pack_h2(o[n][0] * i0, o[n][1] * i0);
        *(uint32_t*)(og + (size_t)row1g * DMODEL + col) =
            pack_h2(o[n][2] * i1, o[n][3] * i1);
    }
}

// ----------------------------------------------------------------------------
// Launch
// ----------------------------------------------------------------------------
extern "C" void kernel_launch(void* const* d_in, const int* in_sizes, int n_in,
                              void* d_out, int out_size) {
    const float* x  = (const float*)d_in[0];
    const float* g  = (const float*)d_in[1];
    const float* wq = (const float*)d_in[2];
    const float* wk = (const float*)d_in[3];
    const float* wv = (const float*)d_in[4];
    const float* wo = (const float*)d_in[5];
    float* out = (float*)d_out;

    static bool inited = false;
    static __half *hh, *wqkvt, *wot, *pqkv, *q16, *k16, *o16;
    static float2 *ropet;
    if (!inited) {
        inited = true;
        cudaFuncSetAttribute(mma_gemm_kernel<true>,
                             cudaFuncAttributeMaxDynamicSharedMemorySize, GEMM_SMEM);
        cudaFuncSetAttribute(mma_gemm_kernel<false>,
                             cudaFuncAttributeMaxDynamicSharedMemorySize, GEMM_SMEM);
        cudaFuncSetAttribute(attn_mma_kernel,
                             cudaFuncAttributeMaxDynamicSharedMemorySize, ATTN_SMEM);
        cudaGetSymbolAddress((void**)&hh,    g_h);
        cudaGetSymbolAddress((void**)&wqkvt, g_wqkvt);
        cudaGetSymbolAddress((void**)&wot,   g_wot);
        cudaGetSymbolAddress((void**)&pqkv,  g_pqkv);
        cudaGetSymbolAddress((void**)&q16,   g_q);
        cudaGetSymbolAddress((void**)&k16,   g_k);
        cudaGetSymbolAddress((void**)&o16,   g_o);
        cudaGetSymbolAddress((void**)&ropet, g_rope_tab);
    }

    // 0) RoPE cos/sin table (fp64 paid once over 65K entries)
    rope_table_kernel<<<(S_LEN * 32 + 255) / 256, 256>>>(ropet);

    // 1) RMSNorm -> fp16
    rmsnorm_kernel<<<S_LEN, 256>>>(x, g, hh);

    // 2) All weight transposes in one launch
    transpose_all_kernel<<<10240, dim3(32, 8)>>>(wq, wk, wv, wo, wqkvt, wot);

    // 3) Fused QKV projection (fp16 out)
    mma_gemm_kernel<true><<<dim3(QKV_N / 128, S_LEN / 128), 256, GEMM_SMEM>>>(
        hh, wqkvt, nullptr, pqkv, QKV_N, DMODEL);

    // 4) RoPE via table (q scaled by 1/sqrt(HD)); V used in place from pqkv
    {
        const int tq = S_LEN * HQ * 16;
        rope_half_kernel<<<(tq + 255) / 256, 256>>>(pqkv, QKV_N, q16, DMODEL, HQ, 0.125f, tq, ropet);
        const int tk = S_LEN * HKV * 16;
        rope_half_kernel<<<(tk + 255) / 256, 256>>>(pqkv + DMODEL, QKV_N, k16, KV_DIM, HKV, 1.0f, tk, ropet);
    }

    // 5) Attention (V strided directly out of pqkv)
    attn_mma_kernel<<<dim3(S_LEN / 128, HQ), 256, ATTN_SMEM>>>(
        q16, k16, pqkv + DMODEL + KV_DIM, QKV_N, o16);

    // 6) Output projection + residual (fp32 out)
    mma_gemm_kernel<false><<<dim3(DMODEL / 128, S_LEN / 128), 256, GEMM_SMEM>>>(
        o16, wot, x, out, DMODEL, DMODEL);
}